// round 16
// baseline (speedup 1.0000x reference)
#include <cuda_runtime.h>
#include <cuda_fp16.h>
#include <cstdint>
#include <math.h>

constexpr int Tn  = 2048;
constexpr int Hn  = 2048;
constexpr int In  = 1024;
constexpr int En  = 8;
constexpr int ISn = 2048;
constexpr int Rn  = 4096;

// ------------------------- scratch (device globals) -------------------------
__device__ __half c_yr [(size_t)Rn * Hn];         // routed down output (fp16)
__device__ __half c_x  [(size_t)Tn * Hn];
__device__ __half c_bu [(size_t)En * Hn * 2048];  // [e][h][(g,u) interleaved]
__device__ __half c_wd [(size_t)En * In * Hn];
__device__ __half c_bs [(size_t)Hn * 4096];       // [h][(g,u) interleaved]
__device__ __half c_sd [(size_t)ISn * Hn];
__device__ __half c_hr [(size_t)Rn * In];
__device__ __half c_hs [(size_t)Tn * ISn];
__device__ int   g_tok[Rn];
__device__ float g_w  [Rn];
__device__ int   g_slot[Rn];
__device__ int   g_topk_i[Rn];
__device__ float g_topk_w[Rn];
__device__ int   g_cnt[En], g_off[En];

// ------------------------- PTX helpers --------------------------------------
__device__ __forceinline__ uint32_t smem_u32(const void* p) {
    uint32_t a;
    asm("{ .reg .u64 t; cvta.to.shared.u64 t, %1; cvt.u32.u64 %0, t; }" : "=r"(a) : "l"(p));
    return a;
}
__device__ __forceinline__ void cpa16(uint32_t dst, const void* src) {
    asm volatile("cp.async.cg.shared.global [%0], [%1], 16;" :: "r"(dst), "l"(src));
}
__device__ __forceinline__ void ldsm4(uint32_t* d, uint32_t a) {
    asm volatile("ldmatrix.sync.aligned.m8n8.x4.shared.b16 {%0,%1,%2,%3},[%4];"
                 : "=r"(d[0]), "=r"(d[1]), "=r"(d[2]), "=r"(d[3]) : "r"(a));
}
__device__ __forceinline__ void ldsm4t(uint32_t* d, uint32_t a) {
    asm volatile("ldmatrix.sync.aligned.m8n8.x4.trans.shared.b16 {%0,%1,%2,%3},[%4];"
                 : "=r"(d[0]), "=r"(d[1]), "=r"(d[2]), "=r"(d[3]) : "r"(a));
}
__device__ __forceinline__ void mma16(float* c, const uint32_t* a, const uint32_t* b) {
    asm volatile(
        "mma.sync.aligned.m16n8k16.row.col.f32.f16.f16.f32 "
        "{%0,%1,%2,%3},{%4,%5,%6,%7},{%8,%9},{%0,%1,%2,%3};"
        : "+f"(c[0]), "+f"(c[1]), "+f"(c[2]), "+f"(c[3])
        : "r"(a[0]), "r"(a[1]), "r"(a[2]), "r"(a[3]), "r"(b[0]), "r"(b[1]));
}
__device__ __forceinline__ uint32_t h2u(float a, float b) {
    __half2 h = __floats2half2_rn(a, b);
    return *reinterpret_cast<uint32_t*>(&h);
}

// ------------------------- conversion helpers --------------------------------
__device__ __forceinline__ void cvt_pair_seg(const float* g, const float* u,
                                             __half* d, int rows, int inner,
                                             int gid, int gstride) {
    int i4 = inner / 4, tot = rows * i4;
    for (int q = gid; q < tot; q += gstride) {
        int r = q / i4, c = (q - r * i4) * 4;
        float4 gv = *reinterpret_cast<const float4*>(g + (size_t)r * inner + c);
        float4 uv = *reinterpret_cast<const float4*>(u + (size_t)r * inner + c);
        uint4 o;
        o.x = h2u(gv.x, uv.x);
        o.y = h2u(gv.y, uv.y);
        o.z = h2u(gv.z, uv.z);
        o.w = h2u(gv.w, uv.w);
        *reinterpret_cast<uint4*>(d + (size_t)r * 2 * inner + 2 * c) = o;
    }
}
__device__ __forceinline__ void cvt_seg(const float* s, __half* d, int n4,
                                        int gid, int gstride) {
    for (int i = gid; i < n4; i += gstride) {
        float4 v = reinterpret_cast<const float4*>(s)[i];
        uint2 o;
        o.x = h2u(v.x, v.y);
        o.y = h2u(v.z, v.w);
        reinterpret_cast<uint2*>(d)[i] = o;
    }
}

// ------------------------- gate (+x->fp16) fused with cvt_bs -----------------
__global__ void k_gate_cvt(const float* __restrict__ x, const float* __restrict__ gw,
                           const float* __restrict__ sg, const float* __restrict__ su) {
    if (blockIdx.x >= 512) {
        // ---- cvt_bs co-tenant CTAs (512 active) ----
        int gid = (blockIdx.x - 512) * 256 + threadIdx.x;
        cvt_pair_seg(sg, su, c_bs, Hn, ISn, gid, 512 * 256);
        return;
    }
    // ---- gate: 2 warps per token ----
    __shared__ float red[4][2][En];
    int wid = threadIdx.x >> 5, lane = threadIdx.x & 31;
    int tp = wid >> 1, hf = wid & 1;
    int t = blockIdx.x * 4 + tp;
    float acc[En];
#pragma unroll
    for (int e = 0; e < En; ++e) acc[e] = 0.f;
    const float4* xr = reinterpret_cast<const float4*>(x + (size_t)t * Hn);
    uint2* xo = reinterpret_cast<uint2*>(c_x + (size_t)t * Hn);
#pragma unroll
    for (int j = 0; j < 8; ++j) {
        int it = hf * 8 + j;
        float4 xv = xr[lane + 32 * it];
        uint2 ov;
        ov.x = h2u(xv.x, xv.y);
        ov.y = h2u(xv.z, xv.w);
        xo[lane + 32 * it] = ov;
#pragma unroll
        for (int e = 0; e < En; ++e) {
            float4 wv = reinterpret_cast<const float4*>(gw + (size_t)e * Hn)[lane + 32 * it];
            acc[e] += xv.x * wv.x + xv.y * wv.y + xv.z * wv.z + xv.w * wv.w;
        }
    }
#pragma unroll
    for (int e = 0; e < En; ++e)
#pragma unroll
        for (int o = 16; o; o >>= 1) acc[e] += __shfl_xor_sync(0xffffffffu, acc[e], o);
    if (lane == 0) {
#pragma unroll
        for (int e = 0; e < En; ++e) red[tp][hf][e] = acc[e];
    }
    __syncthreads();
    if (hf == 0 && lane == 0) {
        float sc[En];
#pragma unroll
        for (int e = 0; e < En; ++e) sc[e] = red[tp][0][e] + red[tp][1][e];
        int i0 = 0; float l0 = sc[0];
#pragma unroll
        for (int e = 1; e < En; ++e) if (sc[e] > l0) { l0 = sc[e]; i0 = e; }
        int i1 = -1; float l1 = -1e30f;
#pragma unroll
        for (int e = 0; e < En; ++e) if (e != i0 && sc[e] > l1) { l1 = sc[e]; i1 = e; }
        float e1 = expf(l1 - l0);
        float w0 = 1.f / (1.f + e1);
        float w1 = e1 / (1.f + e1);
        g_topk_i[2 * t]     = i0; g_topk_w[2 * t]     = w0;
        g_topk_i[2 * t + 1] = i1; g_topk_w[2 * t + 1] = w1;
    }
}

// ------------------------- routing body (single CTA, 256 thr) ----------------
__device__ __forceinline__ void route_body() {
    __shared__ int cnt[En], off[En], cur[En];
    int tid = threadIdx.x;
    if (tid < En) cnt[tid] = 0;
    __syncthreads();
    for (int i = tid; i < Rn; i += 256) atomicAdd(&cnt[g_topk_i[i]], 1);
    __syncthreads();
    if (tid == 0) {
        int s = 0;
        for (int e = 0; e < En; ++e) { off[e] = s; s += cnt[e]; }
    }
    __syncthreads();
    if (tid < En) { g_cnt[tid] = cnt[tid]; g_off[tid] = off[tid]; cur[tid] = 0; }
    __syncthreads();
    for (int i = tid; i < Rn; i += 256) {
        int e = g_topk_i[i];
        int pos = off[e] + atomicAdd(&cur[e], 1);
        g_tok[pos] = i >> 1;
        g_w[pos]   = g_topk_w[i];
        g_slot[i]  = pos;
    }
}

// ------------------------- fp16 mma GEMM body (R8/R12-proven) ----------------
constexpr int ST  = 4;
constexpr int ABY = 128 * 64;
constexpr int BBY = 32 * 256;
constexpr int STG = ABY + BBY;
constexpr int DSM = ST * STG;    // 64KB

template <int VAR>
__device__ __forceinline__ void gemm_body(const __half* __restrict__ Ag,
                                          const __half* __restrict__ Bg,
                                          float* __restrict__ Cg,
                                          __half* __restrict__ Ch,
                                          int tn, int tm, int e) {
    constexpr int  KD   = (VAR == 1) ? 1024 : 2048;
    constexpr int  LDA  = (VAR == 1) ? 1024 : 2048;
    constexpr int  LDB  = (VAR == 2) ? 4096 : 2048;
    constexpr int  LDO  = (VAR == 0) ? 1024 : 2048;
    constexpr bool GROUP  = (VAR < 2);
    constexpr bool GATHER = (VAR == 0);
    constexpr bool COMB   = (VAR == 3);
    constexpr bool SWI    = (VAR == 0 || VAR == 2);
    constexpr int  NIT  = KD / 32;

    int mcount = Tn, mbase = 0;
    if (GROUP) {
        mcount = g_cnt[e];
        if (tm * 128 >= mcount) return;
        mbase = g_off[e];
    }
    const __half* Bp = Bg;
    if (VAR == 0) Bp += (size_t)e * Hn * 2048;
    if (VAR == 1) Bp += (size_t)e * In * 2048;
    const int ncol0 = tn * 128;

    extern __shared__ char smraw[];
    const uint32_t smb = smem_u32(smraw);
    const int tid = threadIdx.x;

    // ---- A source ----
    int lr = tm * 128 + (tid >> 1);
    if (GROUP && lr >= mcount) lr = mcount - 1;
    const __half* arow;
    if (GATHER) arow = Ag + (size_t)g_tok[mbase + lr] * LDA;
    else        arow = Ag + (size_t)(mbase + lr) * LDA;
    arow += (tid & 1) * 16;
    const int arow_s = tid >> 1;
    const int ac0 = (tid & 1) * 2;
    uint32_t dsta0 = arow_s * 64 + (((ac0)     ^ ((arow_s >> 1) & 3)) << 4);
    uint32_t dsta1 = arow_s * 64 + (((ac0 + 1) ^ ((arow_s >> 1) & 3)) << 4);

    // ---- B source ----
    const int bk = tid >> 3;
    const int bc0 = (tid & 7) * 2;
    const __half* bsrc = Bp + (size_t)bk * LDB + ncol0 + bc0 * 8;
    uint32_t dstb0 = ABY + bk * 256 + (((bc0)     ^ (bk & 7)) << 4);
    uint32_t dstb1 = ABY + bk * 256 + (((bc0 + 1) ^ (bk & 7)) << 4);

    auto load_stage = [&](int sl) {
        uint32_t sb = smb + (sl % ST) * STG;
        const __half* as = arow + sl * 32;
        cpa16(sb + dsta0, as);
        cpa16(sb + dsta1, as + 8);
        const __half* bs = bsrc + (size_t)sl * 32 * LDB;
        cpa16(sb + dstb0, bs);
        cpa16(sb + dstb1, bs + 8);
    };

#pragma unroll
    for (int s = 0; s < ST - 1; ++s) {
        if (s < NIT) load_stage(s);
        asm volatile("cp.async.commit_group;" ::: "memory");
    }

    float acc[4][4][4];
#pragma unroll
    for (int i = 0; i < 4; ++i)
#pragma unroll
        for (int j = 0; j < 4; ++j)
#pragma unroll
            for (int k = 0; k < 4; ++k) acc[i][j][k] = 0.f;

    const int w = tid >> 5, l = tid & 31;
    const int wm = (w >> 2) * 64, wn = (w & 3) * 32;
    const int l15 = l & 15, l16 = l >> 4;

    for (int s = 0; s < NIT; ++s) {
        asm volatile("cp.async.wait_group 2;" ::: "memory");
        __syncthreads();
        {
            int sl = s + ST - 1;
            if (sl < NIT) load_stage(sl);
            asm volatile("cp.async.commit_group;" ::: "memory");
        }
        uint32_t ab = smb + (s % ST) * STG, bb = ab + ABY;
#pragma unroll
        for (int ks = 0; ks < 2; ++ks) {
            uint32_t af[4][4], bf[2][4];
#pragma unroll
            for (int mi = 0; mi < 4; ++mi) {
                int m = wm + mi * 16 + l15;
                int c = ks * 2 + l16;
                ldsm4(af[mi], ab + m * 64 + ((c ^ ((m >> 1) & 3)) << 4));
            }
#pragma unroll
            for (int nj = 0; nj < 2; ++nj) {
                int k = ks * 16 + l15;
                int cn = (wn + nj * 16 + l16 * 8) >> 3;
                ldsm4t(bf[nj], bb + k * 256 + ((cn ^ (k & 7)) << 4));
            }
#pragma unroll
            for (int mi = 0; mi < 4; ++mi)
#pragma unroll
                for (int ni = 0; ni < 4; ++ni)
                    mma16(acc[mi][ni], af[mi], &bf[ni >> 1][(ni & 1) * 2]);
        }
    }

    const int qp = l >> 2, qr = l & 3;

    if (SWI) {
        // ---- swiglu epilogue: (g,u) adjacent cols; fp16 staged in smem ----
        __syncthreads();
        __half* sm = reinterpret_cast<__half*>(smraw);   // [128][72]
#pragma unroll
        for (int mi = 0; mi < 4; ++mi) {
#pragma unroll
            for (int h = 0; h < 2; ++h) {
                int row = wm + mi * 16 + qp + h * 8;
                float wgt = 1.f;
                if (GROUP) {
                    int cr = tm * 128 + row;
                    if (cr >= mcount) cr = mcount - 1;
                    wgt = g_w[mbase + cr];
                }
#pragma unroll
                for (int ni = 0; ni < 4; ++ni) {
                    int pi = (wn >> 1) + ni * 4 + qr;
                    float gv = acc[mi][ni][h * 2 + 0];
                    float uv = acc[mi][ni][h * 2 + 1];
                    float o = wgt * (gv / (1.f + expf(-gv))) * uv;
                    sm[row * 72 + pi] = __float2half_rn(o);
                }
            }
        }
        __syncthreads();
        int row = tid >> 1;
        int lrow = tm * 128 + row;
        if (!GROUP || lrow < mcount) {
            size_t rowi = (size_t)(mbase + lrow);
            const uint4* src = reinterpret_cast<const uint4*>(sm + row * 72 + (tid & 1) * 32);
            uint4* dst = reinterpret_cast<uint4*>(Ch + rowi * LDO + tn * 64 + (tid & 1) * 32);
#pragma unroll
            for (int q = 0; q < 4; ++q) dst[q] = src[q];
        }
        return;
    }

    // ---- epilogue (VAR 1: fp16 -> c_yr; VAR 3: f32 out + combine) ----
#pragma unroll
    for (int mi = 0; mi < 4; ++mi) {
#pragma unroll
        for (int h = 0; h < 2; ++h) {
            int lrow = tm * 128 + wm + mi * 16 + qp + h * 8;
            if (GROUP && lrow >= mcount) continue;
            size_t rowi = (size_t)(mbase + lrow);
#pragma unroll
            for (int ni = 0; ni < 4; ++ni) {
                int nc = ncol0 + wn + ni * 8 + 2 * qr;
                float2 v;
                v.x = acc[mi][ni][h * 2 + 0];
                v.y = acc[mi][ni][h * 2 + 1];
                if (VAR == 1) {
                    *reinterpret_cast<uint32_t*>(&c_yr[rowi * Hn + nc]) = h2u(v.x, v.y);
                } else {
                    if (COMB) {
                        int t = (int)rowi;
                        int s0 = g_slot[2 * t], s1 = g_slot[2 * t + 1];
                        uint32_t u0 = *reinterpret_cast<const uint32_t*>(&c_yr[(size_t)s0 * Hn + nc]);
                        uint32_t u1 = *reinterpret_cast<const uint32_t*>(&c_yr[(size_t)s1 * Hn + nc]);
                        __half2 y0 = *reinterpret_cast<__half2*>(&u0);
                        __half2 y1 = *reinterpret_cast<__half2*>(&u1);
                        v.x += __low2float(y0)  + __low2float(y1);
                        v.y += __high2float(y0) + __high2float(y1);
                    }
                    *reinterpret_cast<float2*>(&Cg[rowi * 2048 + nc]) = v;
                }
            }
        }
    }
}

// ------------------------- kernels -------------------------------------------
// Shared up-proj (z==0); z==1: CTAs 0..510 do cvt_bu, CTA 511 does routing.
__global__ __launch_bounds__(256, 2)
void k_gemm_su(const float* __restrict__ wg, const float* __restrict__ wu) {
    if (blockIdx.z == 1) {
        int idx = blockIdx.y * 32 + blockIdx.x;
        if (idx == 511) { route_body(); return; }
        int gid = idx * 256 + threadIdx.x;
        cvt_pair_seg(wg, wu, c_bu, En * Hn, In, gid, 511 * 256);
        return;
    }
    gemm_body<2>(c_x, c_bs, nullptr, c_hs, blockIdx.x, blockIdx.y, 0);
}

// Routed up-proj (z<8) with cvt wd/sd co-tenant CTAs at z==8 (512 active).
__global__ __launch_bounds__(256, 2)
void k_gemm_ru(const float* __restrict__ wd, const float* __restrict__ sd) {
    if (blockIdx.z == 8) {
        int idx = blockIdx.y * 16 + blockIdx.x;
        int gid = idx * 256 + threadIdx.x;
        const int gs = 512 * 256;
        cvt_seg(wd, c_wd, En * In * Hn / 4, gid, gs);
        cvt_seg(sd, c_sd, ISn * Hn / 4, gid, gs);
        return;
    }
    gemm_body<0>(c_x, c_bu, nullptr, c_hr, blockIdx.x, blockIdx.y, blockIdx.z);
}

// Routed down.
__global__ __launch_bounds__(256, 2)
void k_gemm_rd() {
    gemm_body<1>(c_hr, c_wd, nullptr, nullptr, blockIdx.x, blockIdx.y, blockIdx.z);
}

// Shared down + routed combine.
__global__ __launch_bounds__(256, 2)
void k_gemm_sd(float* __restrict__ out) {
    gemm_body<3>(c_hs, c_sd, out, nullptr, blockIdx.x, blockIdx.y, 0);
}

// ------------------------- launch -------------------------------------------
extern "C" void kernel_launch(void* const* d_in, const int* in_sizes, int n_in,
                              void* d_out, int out_size) {
    (void)in_sizes; (void)n_in; (void)out_size;
    const float* x  = (const float*)d_in[0];
    const float* gw = (const float*)d_in[1];
    const float* wg = (const float*)d_in[2];
    const float* wu = (const float*)d_in[3];
    const float* wd = (const float*)d_in[4];
    const float* sg = (const float*)d_in[5];
    const float* su = (const float*)d_in[6];
    const float* sd = (const float*)d_in[7];
    float* out = (float*)d_out;

    cudaFuncSetAttribute(k_gemm_su, cudaFuncAttributeMaxDynamicSharedMemorySize, DSM);
    cudaFuncSetAttribute(k_gemm_ru, cudaFuncAttributeMaxDynamicSharedMemorySize, DSM);
    cudaFuncSetAttribute(k_gemm_rd, cudaFuncAttributeMaxDynamicSharedMemorySize, DSM);
    cudaFuncSetAttribute(k_gemm_sd, cudaFuncAttributeMaxDynamicSharedMemorySize, DSM);

    k_gate_cvt<<<1024, 256>>>(x, gw, sg, su);              // 1: gate + x->f16 + cvt_bs(512)
    k_gemm_su<<<dim3(32, 16, 2), 256, DSM>>>(wg, wu);      // 2: shared up+swiglu (+cvt_bu +route)
    k_gemm_ru<<<dim3(16, 32, 9), 256, DSM>>>(wd, sd);      // 3: routed up+swiglu (+cvt wd/sd)
    k_gemm_rd<<<dim3(16, 32, 8), 256, DSM>>>();            // 4: routed down -> c_yr
    k_gemm_sd<<<dim3(16, 16, 1), 256, DSM>>>(out);         // 5: shared down + combine
}

// round 17
// speedup vs baseline: 1.0258x; 1.0258x over previous
#include <cuda_runtime.h>
#include <cuda_fp16.h>
#include <cstdint>
#include <math.h>

constexpr int Tn  = 2048;
constexpr int Hn  = 2048;
constexpr int In  = 1024;
constexpr int En  = 8;
constexpr int ISn = 2048;
constexpr int Rn  = 4096;

// ------------------------- scratch (device globals) -------------------------
__device__ __half c_yr [(size_t)Rn * Hn];         // routed down output (fp16)
__device__ __half c_x  [(size_t)Tn * Hn];
__device__ __half c_bu [(size_t)En * Hn * 2048];  // [e][h][(g,u) interleaved]
__device__ __half c_wd [(size_t)En * In * Hn];
__device__ __half c_bs [(size_t)Hn * 4096];       // [h][(g,u) interleaved]
__device__ __half c_sd [(size_t)ISn * Hn];
__device__ __half c_hr [(size_t)Rn * In];
__device__ __half c_hs [(size_t)Tn * ISn];
__device__ int   g_tok[Rn];
__device__ float g_w  [Rn];
__device__ int   g_slot[Rn];
__device__ int   g_topk_i[Rn];
__device__ float g_topk_w[Rn];
__device__ int   g_cnt[En], g_off[En];

// ------------------------- PTX helpers --------------------------------------
__device__ __forceinline__ uint32_t smem_u32(const void* p) {
    uint32_t a;
    asm("{ .reg .u64 t; cvta.to.shared.u64 t, %1; cvt.u32.u64 %0, t; }" : "=r"(a) : "l"(p));
    return a;
}
__device__ __forceinline__ void cpa16(uint32_t dst, const void* src) {
    asm volatile("cp.async.cg.shared.global [%0], [%1], 16;" :: "r"(dst), "l"(src));
}
__device__ __forceinline__ void ldsm4(uint32_t* d, uint32_t a) {
    asm volatile("ldmatrix.sync.aligned.m8n8.x4.shared.b16 {%0,%1,%2,%3},[%4];"
                 : "=r"(d[0]), "=r"(d[1]), "=r"(d[2]), "=r"(d[3]) : "r"(a));
}
__device__ __forceinline__ void ldsm4t(uint32_t* d, uint32_t a) {
    asm volatile("ldmatrix.sync.aligned.m8n8.x4.trans.shared.b16 {%0,%1,%2,%3},[%4];"
                 : "=r"(d[0]), "=r"(d[1]), "=r"(d[2]), "=r"(d[3]) : "r"(a));
}
__device__ __forceinline__ void mma16(float* c, const uint32_t* a, const uint32_t* b) {
    asm volatile(
        "mma.sync.aligned.m16n8k16.row.col.f32.f16.f16.f32 "
        "{%0,%1,%2,%3},{%4,%5,%6,%7},{%8,%9},{%0,%1,%2,%3};"
        : "+f"(c[0]), "+f"(c[1]), "+f"(c[2]), "+f"(c[3])
        : "r"(a[0]), "r"(a[1]), "r"(a[2]), "r"(a[3]), "r"(b[0]), "r"(b[1]));
}
__device__ __forceinline__ uint32_t h2u(float a, float b) {
    __half2 h = __floats2half2_rn(a, b);
    return *reinterpret_cast<uint32_t*>(&h);
}

// ------------------------- conversion helpers --------------------------------
__device__ __forceinline__ void cvt_pair_seg(const float* g, const float* u,
                                             __half* d, int rows, int inner,
                                             int gid, int gstride) {
    int i4 = inner / 4, tot = rows * i4;
    for (int q = gid; q < tot; q += gstride) {
        int r = q / i4, c = (q - r * i4) * 4;
        float4 gv = *reinterpret_cast<const float4*>(g + (size_t)r * inner + c);
        float4 uv = *reinterpret_cast<const float4*>(u + (size_t)r * inner + c);
        uint4 o;
        o.x = h2u(gv.x, uv.x);
        o.y = h2u(gv.y, uv.y);
        o.z = h2u(gv.z, uv.z);
        o.w = h2u(gv.w, uv.w);
        *reinterpret_cast<uint4*>(d + (size_t)r * 2 * inner + 2 * c) = o;
    }
}
__device__ __forceinline__ void cvt_seg(const float* s, __half* d, int n4,
                                        int gid, int gstride) {
    for (int i = gid; i < n4; i += gstride) {
        float4 v = reinterpret_cast<const float4*>(s)[i];
        uint2 o;
        o.x = h2u(v.x, v.y);
        o.y = h2u(v.z, v.w);
        reinterpret_cast<uint2*>(d)[i] = o;
    }
}

// ------------------------- gate (+x->fp16) fused with cvt_bs -----------------
__global__ void k_gate_cvt(const float* __restrict__ x, const float* __restrict__ gw,
                           const float* __restrict__ sg, const float* __restrict__ su) {
    if (blockIdx.x >= 512) {
        // ---- cvt_bs co-tenant CTAs ----
        int gid = (blockIdx.x - 512) * 256 + threadIdx.x;
        cvt_pair_seg(sg, su, c_bs, Hn, ISn, gid, 512 * 256);
        return;
    }
    // ---- gate: 2 warps per token ----
    __shared__ float red[4][2][En];
    int wid = threadIdx.x >> 5, lane = threadIdx.x & 31;
    int tp = wid >> 1, hf = wid & 1;
    int t = blockIdx.x * 4 + tp;
    float acc[En];
#pragma unroll
    for (int e = 0; e < En; ++e) acc[e] = 0.f;
    const float4* xr = reinterpret_cast<const float4*>(x + (size_t)t * Hn);
    uint2* xo = reinterpret_cast<uint2*>(c_x + (size_t)t * Hn);
#pragma unroll
    for (int j = 0; j < 8; ++j) {
        int it = hf * 8 + j;
        float4 xv = xr[lane + 32 * it];
        uint2 ov;
        ov.x = h2u(xv.x, xv.y);
        ov.y = h2u(xv.z, xv.w);
        xo[lane + 32 * it] = ov;
#pragma unroll
        for (int e = 0; e < En; ++e) {
            float4 wv = reinterpret_cast<const float4*>(gw + (size_t)e * Hn)[lane + 32 * it];
            acc[e] += xv.x * wv.x + xv.y * wv.y + xv.z * wv.z + xv.w * wv.w;
        }
    }
#pragma unroll
    for (int e = 0; e < En; ++e)
#pragma unroll
        for (int o = 16; o; o >>= 1) acc[e] += __shfl_xor_sync(0xffffffffu, acc[e], o);
    if (lane == 0) {
#pragma unroll
        for (int e = 0; e < En; ++e) red[tp][hf][e] = acc[e];
    }
    __syncthreads();
    if (hf == 0 && lane == 0) {
        float sc[En];
#pragma unroll
        for (int e = 0; e < En; ++e) sc[e] = red[tp][0][e] + red[tp][1][e];
        int i0 = 0; float l0 = sc[0];
#pragma unroll
        for (int e = 1; e < En; ++e) if (sc[e] > l0) { l0 = sc[e]; i0 = e; }
        int i1 = -1; float l1 = -1e30f;
#pragma unroll
        for (int e = 0; e < En; ++e) if (e != i0 && sc[e] > l1) { l1 = sc[e]; i1 = e; }
        float e1 = expf(l1 - l0);
        float w0 = 1.f / (1.f + e1);
        float w1 = e1 / (1.f + e1);
        g_topk_i[2 * t]     = i0; g_topk_w[2 * t]     = w0;
        g_topk_i[2 * t + 1] = i1; g_topk_w[2 * t + 1] = w1;
    }
}

// ------------------------- fused routing (single CTA) ------------------------
__global__ void k_route() {
    __shared__ int cnt[En], off[En], cur[En];
    int tid = threadIdx.x;
    if (tid < En) cnt[tid] = 0;
    __syncthreads();
    for (int i = tid; i < Rn; i += 256) atomicAdd(&cnt[g_topk_i[i]], 1);
    __syncthreads();
    if (tid == 0) {
        int s = 0;
        for (int e = 0; e < En; ++e) { off[e] = s; s += cnt[e]; }
    }
    __syncthreads();
    if (tid < En) { g_cnt[tid] = cnt[tid]; g_off[tid] = off[tid]; cur[tid] = 0; }
    __syncthreads();
    for (int i = tid; i < Rn; i += 256) {
        int e = g_topk_i[i];
        int pos = off[e] + atomicAdd(&cur[e], 1);
        g_tok[pos] = i >> 1;
        g_w[pos]   = g_topk_w[i];
        g_slot[i]  = pos;
    }
}

// ------------------------- fp16 mma GEMM body (R8/R12-proven) ----------------
constexpr int ST  = 4;
constexpr int ABY = 128 * 64;
constexpr int BBY = 32 * 256;
constexpr int STG = ABY + BBY;
constexpr int DSM = ST * STG;    // 64KB

template <int VAR>
__device__ __forceinline__ void gemm_body(const __half* __restrict__ Ag,
                                          const __half* __restrict__ Bg,
                                          float* __restrict__ Cg,
                                          __half* __restrict__ Ch,
                                          int tn, int tm, int e) {
    constexpr int  KD   = (VAR == 1) ? 1024 : 2048;
    constexpr int  LDA  = (VAR == 1) ? 1024 : 2048;
    constexpr int  LDB  = (VAR == 2) ? 4096 : 2048;
    constexpr int  LDO  = (VAR == 0) ? 1024 : 2048;
    constexpr bool GROUP  = (VAR < 2);
    constexpr bool GATHER = (VAR == 0);
    constexpr bool COMB   = (VAR == 3);
    constexpr bool SWI    = (VAR == 0 || VAR == 2);
    constexpr int  NIT  = KD / 32;

    int mcount = Tn, mbase = 0;
    if (GROUP) {
        mcount = g_cnt[e];
        if (tm * 128 >= mcount) return;
        mbase = g_off[e];
    }
    const __half* Bp = Bg;
    if (VAR == 0) Bp += (size_t)e * Hn * 2048;
    if (VAR == 1) Bp += (size_t)e * In * 2048;
    const int ncol0 = tn * 128;

    extern __shared__ char smraw[];
    const uint32_t smb = smem_u32(smraw);
    const int tid = threadIdx.x;

    // ---- A source ----
    int lr = tm * 128 + (tid >> 1);
    if (GROUP && lr >= mcount) lr = mcount - 1;
    const __half* arow;
    if (GATHER) arow = Ag + (size_t)g_tok[mbase + lr] * LDA;
    else        arow = Ag + (size_t)(mbase + lr) * LDA;
    arow += (tid & 1) * 16;
    const int arow_s = tid >> 1;
    const int ac0 = (tid & 1) * 2;
    uint32_t dsta0 = arow_s * 64 + (((ac0)     ^ ((arow_s >> 1) & 3)) << 4);
    uint32_t dsta1 = arow_s * 64 + (((ac0 + 1) ^ ((arow_s >> 1) & 3)) << 4);

    // ---- B source ----
    const int bk = tid >> 3;
    const int bc0 = (tid & 7) * 2;
    const __half* bsrc = Bp + (size_t)bk * LDB + ncol0 + bc0 * 8;
    uint32_t dstb0 = ABY + bk * 256 + (((bc0)     ^ (bk & 7)) << 4);
    uint32_t dstb1 = ABY + bk * 256 + (((bc0 + 1) ^ (bk & 7)) << 4);

    auto load_stage = [&](int sl) {
        uint32_t sb = smb + (sl % ST) * STG;
        const __half* as = arow + sl * 32;
        cpa16(sb + dsta0, as);
        cpa16(sb + dsta1, as + 8);
        const __half* bs = bsrc + (size_t)sl * 32 * LDB;
        cpa16(sb + dstb0, bs);
        cpa16(sb + dstb1, bs + 8);
    };

#pragma unroll
    for (int s = 0; s < ST - 1; ++s) {
        if (s < NIT) load_stage(s);
        asm volatile("cp.async.commit_group;" ::: "memory");
    }

    float acc[4][4][4];
#pragma unroll
    for (int i = 0; i < 4; ++i)
#pragma unroll
        for (int j = 0; j < 4; ++j)
#pragma unroll
            for (int k = 0; k < 4; ++k) acc[i][j][k] = 0.f;

    const int w = tid >> 5, l = tid & 31;
    const int wm = (w >> 2) * 64, wn = (w & 3) * 32;
    const int l15 = l & 15, l16 = l >> 4;

    for (int s = 0; s < NIT; ++s) {
        asm volatile("cp.async.wait_group 2;" ::: "memory");
        __syncthreads();
        {
            int sl = s + ST - 1;
            if (sl < NIT) load_stage(sl);
            asm volatile("cp.async.commit_group;" ::: "memory");
        }
        uint32_t ab = smb + (s % ST) * STG, bb = ab + ABY;
#pragma unroll
        for (int ks = 0; ks < 2; ++ks) {
            uint32_t af[4][4], bf[2][4];
#pragma unroll
            for (int mi = 0; mi < 4; ++mi) {
                int m = wm + mi * 16 + l15;
                int c = ks * 2 + l16;
                ldsm4(af[mi], ab + m * 64 + ((c ^ ((m >> 1) & 3)) << 4));
            }
#pragma unroll
            for (int nj = 0; nj < 2; ++nj) {
                int k = ks * 16 + l15;
                int cn = (wn + nj * 16 + l16 * 8) >> 3;
                ldsm4t(bf[nj], bb + k * 256 + ((cn ^ (k & 7)) << 4));
            }
#pragma unroll
            for (int mi = 0; mi < 4; ++mi)
#pragma unroll
                for (int ni = 0; ni < 4; ++ni)
                    mma16(acc[mi][ni], af[mi], &bf[ni >> 1][(ni & 1) * 2]);
        }
    }

    const int qp = l >> 2, qr = l & 3;

    if (SWI) {
        // ---- swiglu epilogue: (g,u) adjacent cols; fp16 staged in smem ----
        __syncthreads();
        __half* sm = reinterpret_cast<__half*>(smraw);   // [128][72]
#pragma unroll
        for (int mi = 0; mi < 4; ++mi) {
#pragma unroll
            for (int h = 0; h < 2; ++h) {
                int row = wm + mi * 16 + qp + h * 8;
                float wgt = 1.f;
                if (GROUP) {
                    int cr = tm * 128 + row;
                    if (cr >= mcount) cr = mcount - 1;
                    wgt = g_w[mbase + cr];
                }
#pragma unroll
                for (int ni = 0; ni < 4; ++ni) {
                    int pi = (wn >> 1) + ni * 4 + qr;
                    float gv = acc[mi][ni][h * 2 + 0];
                    float uv = acc[mi][ni][h * 2 + 1];
                    float o = wgt * (gv / (1.f + expf(-gv))) * uv;
                    sm[row * 72 + pi] = __float2half_rn(o);
                }
            }
        }
        __syncthreads();
        int row = tid >> 1;
        int lrow = tm * 128 + row;
        if (!GROUP || lrow < mcount) {
            size_t rowi = (size_t)(mbase + lrow);
            const uint4* src = reinterpret_cast<const uint4*>(sm + row * 72 + (tid & 1) * 32);
            uint4* dst = reinterpret_cast<uint4*>(Ch + rowi * LDO + tn * 64 + (tid & 1) * 32);
#pragma unroll
            for (int q = 0; q < 4; ++q) dst[q] = src[q];
        }
        return;
    }

    // ---- epilogue (VAR 1: fp16 -> c_yr; VAR 3: f32 out + combine) ----
#pragma unroll
    for (int mi = 0; mi < 4; ++mi) {
#pragma unroll
        for (int h = 0; h < 2; ++h) {
            int lrow = tm * 128 + wm + mi * 16 + qp + h * 8;
            if (GROUP && lrow >= mcount) continue;
            size_t rowi = (size_t)(mbase + lrow);
#pragma unroll
            for (int ni = 0; ni < 4; ++ni) {
                int nc = ncol0 + wn + ni * 8 + 2 * qr;
                float2 v;
                v.x = acc[mi][ni][h * 2 + 0];
                v.y = acc[mi][ni][h * 2 + 1];
                if (VAR == 1) {
                    *reinterpret_cast<uint32_t*>(&c_yr[rowi * Hn + nc]) = h2u(v.x, v.y);
                } else {
                    if (COMB) {
                        int t = (int)rowi;
                        int s0 = g_slot[2 * t], s1 = g_slot[2 * t + 1];
                        uint32_t u0 = *reinterpret_cast<const uint32_t*>(&c_yr[(size_t)s0 * Hn + nc]);
                        uint32_t u1 = *reinterpret_cast<const uint32_t*>(&c_yr[(size_t)s1 * Hn + nc]);
                        __half2 y0 = *reinterpret_cast<__half2*>(&u0);
                        __half2 y1 = *reinterpret_cast<__half2*>(&u1);
                        v.x += __low2float(y0)  + __low2float(y1);
                        v.y += __high2float(y0) + __high2float(y1);
                    }
                    *reinterpret_cast<float2*>(&Cg[rowi * 2048 + nc]) = v;
                }
            }
        }
    }
}

// ------------------------- kernels -------------------------------------------
// Shared up-proj (z==0) with cvt_bu co-tenant CTAs at z==1 (512 active).
__global__ __launch_bounds__(256, 2)
void k_gemm_su(const float* __restrict__ wg, const float* __restrict__ wu) {
    if (blockIdx.z == 1) {
        int gid = (blockIdx.y * 32 + blockIdx.x) * 256 + threadIdx.x;
        cvt_pair_seg(wg, wu, c_bu, En * Hn, In, gid, 512 * 256);
        return;
    }
    gemm_body<2>(c_x, c_bs, nullptr, c_hs, blockIdx.x, blockIdx.y, 0);
}

// Routed up-proj (z<8) with cvt wd/sd co-tenant CTAs at z==8 (512 active).
__global__ __launch_bounds__(256, 2)
void k_gemm_ru(const float* __restrict__ wd, const float* __restrict__ sd) {
    if (blockIdx.z == 8) {
        int gid = (blockIdx.y * 16 + blockIdx.x) * 256 + threadIdx.x;
        const int gs = 512 * 256;
        cvt_seg(wd, c_wd, En * In * Hn / 4, gid, gs);
        cvt_seg(sd, c_sd, ISn * Hn / 4, gid, gs);
        return;
    }
    gemm_body<0>(c_x, c_bu, nullptr, c_hr, blockIdx.x, blockIdx.y, blockIdx.z);
}

// Routed down.
__global__ __launch_bounds__(256, 2)
void k_gemm_rd() {
    gemm_body<1>(c_hr, c_wd, nullptr, nullptr, blockIdx.x, blockIdx.y, blockIdx.z);
}

// Shared down + routed combine.
__global__ __launch_bounds__(256, 2)
void k_gemm_sd(float* __restrict__ out) {
    gemm_body<3>(c_hs, c_sd, out, nullptr, blockIdx.x, blockIdx.y, 0);
}

// ------------------------- launch -------------------------------------------
extern "C" void kernel_launch(void* const* d_in, const int* in_sizes, int n_in,
                              void* d_out, int out_size) {
    (void)in_sizes; (void)n_in; (void)out_size;
    const float* x  = (const float*)d_in[0];
    const float* gw = (const float*)d_in[1];
    const float* wg = (const float*)d_in[2];
    const float* wu = (const float*)d_in[3];
    const float* wd = (const float*)d_in[4];
    const float* sg = (const float*)d_in[5];
    const float* su = (const float*)d_in[6];
    const float* sd = (const float*)d_in[7];
    float* out = (float*)d_out;

    cudaFuncSetAttribute(k_gemm_su, cudaFuncAttributeMaxDynamicSharedMemorySize, DSM);
    cudaFuncSetAttribute(k_gemm_ru, cudaFuncAttributeMaxDynamicSharedMemorySize, DSM);
    cudaFuncSetAttribute(k_gemm_rd, cudaFuncAttributeMaxDynamicSharedMemorySize, DSM);
    cudaFuncSetAttribute(k_gemm_sd, cudaFuncAttributeMaxDynamicSharedMemorySize, DSM);

    k_gate_cvt<<<1024, 256>>>(x, gw, sg, su);              // 1: gate + x->f16 + cvt_bs(512)
    k_route<<<1, 256>>>();                                 // 2
    k_gemm_su<<<dim3(32, 16, 2), 256, DSM>>>(wg, wu);      // 3: shared up+swiglu (+cvt_bu x512)
    k_gemm_ru<<<dim3(16, 32, 9), 256, DSM>>>(wd, sd);      // 4: routed up+swiglu (+cvt wd/sd x512)
    k_gemm_rd<<<dim3(16, 32, 8), 256, DSM>>>();            // 5: routed down -> c_yr
    k_gemm_sd<<<dim3(16, 16, 1), 256, DSM>>>(out);         // 6: shared down + combine
}